// round 17
// baseline (speedup 1.0000x reference)
#include <cuda_runtime.h>
#include <math.h>

// Problem shape
#define HDIM     4096
#define EDIM     64
#define M_TOTAL  16384
#define BM       128
#define KT       64
#define NTHREADS 256

// Work decomposition: 128 row-tiles x 64 K-chunks = 8192 quanta over 148 CTAs.
// CTA b < 52 gets 56 quanta, else 55 (52*56 + 96*55 = 8192, 1.8% imbalance).
// A span (<64) covers <=2 row tiles -> <=2 partial flushes per CTA.
#define NCTA1    148

__device__ float g_part[NCTA1 * 2 * BM * EDIM];   // per-CTA partial logits, row-major 128x64

__device__ __forceinline__ int chunk_start(int b) {
    return b < 52 ? b * 56 : 2912 + (b - 52) * 55;
}
__device__ __forceinline__ int bid_of_chunk(int c) {
    return c < 2912 ? c / 56 : 52 + (c - 2912) / 55;
}

// ---------------------------------------------------------------------------
// Kernel 1: GEMM over this CTA's quantum span; flush partial logits per tile.
// Inner loop / swizzle / lane maps identical to the proven 182.8us kernel.
// ---------------------------------------------------------------------------
__global__ __launch_bounds__(NTHREADS, 1)
void gemm_part_kernel(const float* __restrict__ x,
                      const float* __restrict__ w)
{
    __shared__ union {
        struct {
            float xs[KT][BM];      // 32 KB
            float ws[KT][EDIM];    // 16 KB
        } t;
        float ls[BM][EDIM + 4];    // flush staging (stride 68)
    } sm;

    const int tid   = threadIdx.x;
    const int bid   = blockIdx.x;
    const int start = chunk_start(bid);
    const int count = bid < 52 ? 56 : 55;
    const int end   = start + count;

    const int eg = tid & 15;           // experts 4*eg .. 4*eg+3
    const int rg = tid >> 4;           // rows    8*rg .. 8*rg+7
    const int xk4   = tid & 7;
    const int xrow0 = tid >> 3;
    const int wk4 = tid & 7;
    const int we0 = tid >> 3;
    const int xsw = 4 * xk4;
    const int wsw = 4 * wk4;

    unsigned long long acc[4][4];
    #pragma unroll
    for (int i = 0; i < 4; i++)
        #pragma unroll
        for (int j = 0; j < 4; j++)
            acc[i][j] = 0ull;

    float4 xv[4][2], wv[2][2];

    // prefetch first chunk
    {
        const int m0 = (start >> 6) * BM;
        const int k0 = (start & 63) * KT;
        const float* xp = x + (size_t)m0 * HDIM + k0 + 4 * xk4;
        #pragma unroll
        for (int i = 0; i < 4; i++) {
            const float* p = xp + (size_t)(xrow0 + 32 * i) * HDIM;
            xv[i][0] = *(const float4*)(p);
            xv[i][1] = *(const float4*)(p + 32);
        }
        const float* wp = w + k0 + 4 * wk4;
        #pragma unroll
        for (int i = 0; i < 2; i++) {
            const float* p = wp + (size_t)(we0 + 32 * i) * HDIM;
            wv[i][0] = *(const float4*)(p);
            wv[i][1] = *(const float4*)(p + 32);
        }
    }

    int slot = 0;
    for (int c = start; c < end; c++) {
        // ---- STS prefetched tile (swizzled transpose, conflict-free) ----
        #pragma unroll
        for (int i = 0; i < 4; i++) {
            int rs = (xrow0 + 32 * i) ^ xsw;
            #pragma unroll
            for (int h = 0; h < 2; h++) {
                int kb = 4 * xk4 + 32 * h;
                sm.t.xs[kb + 0][rs] = xv[i][h].x;
                sm.t.xs[kb + 1][rs] = xv[i][h].y;
                sm.t.xs[kb + 2][rs] = xv[i][h].z;
                sm.t.xs[kb + 3][rs] = xv[i][h].w;
            }
        }
        #pragma unroll
        for (int i = 0; i < 2; i++) {
            int es = (we0 + 32 * i) ^ wsw;
            #pragma unroll
            for (int h = 0; h < 2; h++) {
                int kb = 4 * wk4 + 32 * h;
                sm.t.ws[kb + 0][es] = wv[i][h].x;
                sm.t.ws[kb + 1][es] = wv[i][h].y;
                sm.t.ws[kb + 2][es] = wv[i][h].z;
                sm.t.ws[kb + 3][es] = wv[i][h].w;
            }
        }
        __syncthreads();

        // ---- prefetch next chunk (may belong to the next row tile) ----
        if (c + 1 < end) {
            const int m0n = ((c + 1) >> 6) * BM;
            const int k0n = ((c + 1) & 63) * KT;
            const float* xp = x + (size_t)m0n * HDIM + k0n + 4 * xk4;
            #pragma unroll
            for (int i = 0; i < 4; i++) {
                const float* p = xp + (size_t)(xrow0 + 32 * i) * HDIM;
                xv[i][0] = *(const float4*)(p);
                xv[i][1] = *(const float4*)(p + 32);
            }
            const float* wp = w + k0n + 4 * wk4;
            #pragma unroll
            for (int i = 0; i < 2; i++) {
                const float* p = wp + (size_t)(we0 + 32 * i) * HDIM;
                wv[i][0] = *(const float4*)(p);
                wv[i][1] = *(const float4*)(p + 32);
            }
        }

        // ---- compute: 64 kk steps, 16 fma.rn.f32x2 each ----
        #pragma unroll
        for (int kk = 0; kk < KT; kk++) {
            const int cc = ((kk >> 2) & 7) << 2;
            const int r1 = (8 * rg) ^ cc;
            ulonglong2 xa = *(const ulonglong2*)&sm.t.xs[kk][r1];
            ulonglong2 xb = *(const ulonglong2*)&sm.t.xs[kk][r1 ^ 4];
            float4 wf = *(const float4*)&sm.t.ws[kk][(4 * eg) ^ cc];

            unsigned long long xr[4];
            xr[0] = xa.x; xr[1] = xa.y; xr[2] = xb.x; xr[3] = xb.y;

            unsigned long long wd[4];
            asm("mov.b64 %0, {%1,%1};" : "=l"(wd[0]) : "r"(__float_as_uint(wf.x)));
            asm("mov.b64 %0, {%1,%1};" : "=l"(wd[1]) : "r"(__float_as_uint(wf.y)));
            asm("mov.b64 %0, {%1,%1};" : "=l"(wd[2]) : "r"(__float_as_uint(wf.z)));
            asm("mov.b64 %0, {%1,%1};" : "=l"(wd[3]) : "r"(__float_as_uint(wf.w)));

            #pragma unroll
            for (int rp = 0; rp < 4; rp++)
                #pragma unroll
                for (int e = 0; e < 4; e++)
                    asm("fma.rn.f32x2 %0, %1, %2, %0;"
                        : "+l"(acc[rp][e])
                        : "l"(xr[rp]), "l"(wd[e]));
        }
        __syncthreads();

        // ---- flush partial at tile boundary or span end ----
        if (((c & 63) == 63) || (c + 1 == end)) {
            #pragma unroll
            for (int rp = 0; rp < 4; rp++) {
                #pragma unroll
                for (int e = 0; e < 4; e++) {
                    unsigned int lo, hi;
                    asm("mov.b64 {%0,%1}, %2;" : "=r"(lo), "=r"(hi) : "l"(acc[rp][e]));
                    int r   = 8 * rg + 2 * rp;
                    int col = 4 * eg + e;
                    sm.ls[r][col]     = __uint_as_float(lo);
                    sm.ls[r + 1][col] = __uint_as_float(hi);
                    acc[rp][e] = 0ull;
                }
            }
            __syncthreads();
            float* dst = g_part + (size_t)(bid * 2 + slot) * (BM * EDIM);
            #pragma unroll
            for (int q = 0; q < 8; q++) {
                int idx = tid + NTHREADS * q;
                int row = idx >> 4;
                int c4  = idx & 15;
                *(float4*)&dst[row * EDIM + c4 * 4] = *(const float4*)&sm.ls[row][c4 * 4];
            }
            slot++;
            __syncthreads();   // ls reads done before next STS overwrites the union
        }
    }
}

// ---------------------------------------------------------------------------
// Kernel 2: per row-tile, sum partials in fixed ascending-bid (= K) order,
// write logits, top-2 + softmax. Fully deterministic.
// ---------------------------------------------------------------------------
__global__ __launch_bounds__(NTHREADS, 1)
void combine_kernel(float* __restrict__ out)
{
    __shared__ float ls[BM][EDIM + 4];
    const int T   = blockIdx.x;
    const int tid = threadIdx.x;
    const int b0  = bid_of_chunk(T * 64);
    const int b1  = bid_of_chunk(T * 64 + 63);

    float4 s[8];
    #pragma unroll
    for (int q = 0; q < 8; q++) s[q] = make_float4(0.f, 0.f, 0.f, 0.f);

    for (int b = b0; b <= b1; b++) {
        const int slot = ((chunk_start(b) >> 6) == T) ? 0 : 1;
        const float* src = g_part + (size_t)(b * 2 + slot) * (BM * EDIM);
        #pragma unroll
        for (int q = 0; q < 8; q++) {
            int idx = tid + NTHREADS * q;
            float4 v = *(const float4*)&src[idx * 4];
            s[q].x += v.x; s[q].y += v.y; s[q].z += v.z; s[q].w += v.w;
        }
    }

    float* logits_out = out;
    float* idx_out    = out + (size_t)M_TOTAL * EDIM;
    float* p_out      = idx_out + (size_t)M_TOTAL * 2;
    const int m0 = T * BM;

    #pragma unroll
    for (int q = 0; q < 8; q++) {
        int idx = tid + NTHREADS * q;
        int row = idx >> 4;
        int c4  = idx & 15;
        *(float4*)&ls[row][c4 * 4] = s[q];
        *(float4*)&logits_out[(size_t)(m0 + row) * EDIM + c4 * 4] = s[q];
    }
    __syncthreads();

    // one thread per row: stable top-2 (strict >, ties -> lower index = lax.top_k)
    if (tid < BM) {
        const float* r = &ls[tid][0];
        float best = -INFINITY, sec = -INFINITY;
        int bi = 0, si = 0;
        #pragma unroll 8
        for (int i = 0; i < EDIM; i++) {
            float v = r[i];
            if (v > best) { sec = best; si = bi; best = v; bi = i; }
            else if (v > sec) { sec = v; si = i; }
        }
        float tt  = expf(sec - best);
        float inv = 1.0f / (1.0f + tt);
        size_t m = (size_t)(m0 + tid);
        idx_out[m * 2 + 0] = (float)bi;
        idx_out[m * 2 + 1] = (float)si;
        p_out[m * 2 + 0]   = inv;
        p_out[m * 2 + 1]   = tt * inv;
    }
}

extern "C" void kernel_launch(void* const* d_in, const int* in_sizes, int n_in,
                              void* d_out, int out_size)
{
    const float* x  = (const float*)d_in[0];
    const float* gw = (const float*)d_in[1];
    // defensive: identify tensors by size (x = 67108864, gate_w = 262144)
    if (n_in >= 2 && in_sizes[0] < in_sizes[1]) {
        const float* tmp = x; x = gw; gw = tmp;
    }
    gemm_part_kernel<<<NCTA1, NTHREADS>>>(x, gw);
    combine_kernel<<<M_TOTAL / BM, NTHREADS>>>((float*)d_out);
}